// round 4
// baseline (speedup 1.0000x reference)
#include <cuda_runtime.h>
#include <cstdint>
#include <cstddef>

// ---------------------------------------------------------------------------
// Problem constants
// ---------------------------------------------------------------------------
#define E_DIM   1024
#define H_HEADS 16
#define D_HEAD  64
#define NTOK    8192          // B*S = 16*512
#define NROWS   49152         // 6 * NTOK
#define HID     1024

// ---------------------------------------------------------------------------
// Scratch: one big __device__ array (no cudaMalloc allowed).
// Layout (floats):
//   Q : [0,               50331648)   (reused as O-proj output later)
//   K : [50331648,       100663296)
//   V : [100663296,      150994944)
//   C : [150994944,      201326592)   (attention context)
//   F : [201326592,      209715200)   (fused, 8192x1024)
//   H : [209715200,      218103808)   (pre-LN2 hidden, 8192x1024)
// ---------------------------------------------------------------------------
#define OFF_Q 0ull
#define OFF_K 50331648ull
#define OFF_V 100663296ull
#define OFF_C 150994944ull
#define OFF_O OFF_Q
#define OFF_F 201326592ull
#define OFF_H 209715200ull

__device__ float g_scratch[218103808];

// ---------------------------------------------------------------------------
// SGEMM (NT): C[m,n] = sum_k A[m,k] * W[n,k] + bias[n]   (optional LeakyReLU)
// A: MxK row-major, W: NxK row-major. All dims multiples of tile sizes.
// BM=128, BN=128, BK=16, 256 threads, 8x8 register tile per thread.
// ---------------------------------------------------------------------------
#define BM 128
#define BN 128
#define BK 16

__global__ __launch_bounds__(256)
void sgemm_nt(const float* __restrict__ A, const float* __restrict__ W,
              const float* __restrict__ bias, float* __restrict__ C,
              int M, int N, int K, int act)
{
    __shared__ __align__(16) float As[BK][BM + 4];
    __shared__ __align__(16) float Bs[BK][BN + 4];

    const int tid = threadIdx.x;
    const int m0  = blockIdx.y * BM;
    const int n0  = blockIdx.x * BN;
    const int tx  = tid & 15;         // 0..15
    const int ty  = tid >> 4;         // 0..15

    float acc[8][8];
#pragma unroll
    for (int i = 0; i < 8; i++)
#pragma unroll
        for (int j = 0; j < 8; j++) acc[i][j] = 0.f;

    for (int k0 = 0; k0 < K; k0 += BK) {
        // Load 128x16 tiles of A and W (512 float4 each; 2 per thread),
        // storing transposed so compute reads are vectorized.
#pragma unroll
        for (int i = 0; i < 2; i++) {
            int lin = tid + i * 256;          // 0..511
            int row = lin >> 2;               // 0..127
            int kc  = (lin & 3) << 2;         // 0,4,8,12
            float4 a = *(const float4*)(A + (size_t)(m0 + row) * K + k0 + kc);
            As[kc + 0][row] = a.x;
            As[kc + 1][row] = a.y;
            As[kc + 2][row] = a.z;
            As[kc + 3][row] = a.w;
            float4 b = *(const float4*)(W + (size_t)(n0 + row) * K + k0 + kc);
            Bs[kc + 0][row] = b.x;
            Bs[kc + 1][row] = b.y;
            Bs[kc + 2][row] = b.z;
            Bs[kc + 3][row] = b.w;
        }
        __syncthreads();

#pragma unroll
        for (int kk = 0; kk < BK; kk++) {
            float a[8], b[8];
            *(float4*)&a[0] = *(const float4*)&As[kk][ty * 8];
            *(float4*)&a[4] = *(const float4*)&As[kk][ty * 8 + 4];
            *(float4*)&b[0] = *(const float4*)&Bs[kk][tx * 8];
            *(float4*)&b[4] = *(const float4*)&Bs[kk][tx * 8 + 4];
#pragma unroll
            for (int i = 0; i < 8; i++)
#pragma unroll
                for (int j = 0; j < 8; j++)
                    acc[i][j] += a[i] * b[j];
        }
        __syncthreads();
    }

    // Epilogue: bias (+ optional LeakyReLU), vectorized stores.
#pragma unroll
    for (int i = 0; i < 8; i++) {
        size_t crow = (size_t)(m0 + ty * 8 + i) * N + n0 + tx * 8;
#pragma unroll
        for (int jj = 0; jj < 8; jj += 4) {
            float4 bsv = *(const float4*)(bias + n0 + tx * 8 + jj);
            float4 o;
            o.x = acc[i][jj + 0] + bsv.x;
            o.y = acc[i][jj + 1] + bsv.y;
            o.z = acc[i][jj + 2] + bsv.z;
            o.w = acc[i][jj + 3] + bsv.w;
            if (act) {
                o.x = o.x >= 0.f ? o.x : 0.01f * o.x;
                o.y = o.y >= 0.f ? o.y : 0.01f * o.y;
                o.z = o.z >= 0.f ? o.z : 0.01f * o.z;
                o.w = o.w >= 0.f ? o.w : 0.01f * o.w;
            }
            *(float4*)(C + crow + jj) = o;
        }
    }
}

// ---------------------------------------------------------------------------
// Tiny 6x6 attention: one warp per (token n, head h).
// Q/K/V layout: row r = j*NTOK + n, cols = h*64 + d.
// ---------------------------------------------------------------------------
__device__ __forceinline__ float warpAllSum(float v)
{
#pragma unroll
    for (int o = 16; o; o >>= 1) v += __shfl_xor_sync(0xffffffffu, v, o);
    return v;
}

__global__ __launch_bounds__(256)
void attn6_kernel(const float* __restrict__ Q, const float* __restrict__ K,
                  const float* __restrict__ V, float* __restrict__ C)
{
    const int warp = threadIdx.x >> 5;
    const int lane = threadIdx.x & 31;
    const int idx  = blockIdx.x * 8 + warp;    // 0 .. NTOK*H_HEADS-1
    const int n = idx >> 4;
    const int h = idx & 15;

    const size_t base = (size_t)n * E_DIM + h * D_HEAD + 2 * lane;

    float2 q[6], k[6], v[6];
#pragma unroll
    for (int j = 0; j < 6; j++) {
        size_t off = base + (size_t)j * NTOK * E_DIM;
        q[j] = *(const float2*)(Q + off);
        k[j] = *(const float2*)(K + off);
        v[j] = *(const float2*)(V + off);
    }

    float s[6][6];
#pragma unroll
    for (int i = 0; i < 6; i++)
#pragma unroll
        for (int j = 0; j < 6; j++) {
            float p = q[i].x * k[j].x + q[i].y * k[j].y;
            s[i][j] = warpAllSum(p) * 0.125f;      // 1/sqrt(64)
        }

#pragma unroll
    for (int i = 0; i < 6; i++) {
        float mx = s[i][0];
#pragma unroll
        for (int j = 1; j < 6; j++) mx = fmaxf(mx, s[i][j]);
        float se = 0.f;
#pragma unroll
        for (int j = 0; j < 6; j++) { s[i][j] = __expf(s[i][j] - mx); se += s[i][j]; }
        float inv = 1.f / se;
#pragma unroll
        for (int j = 0; j < 6; j++) s[i][j] *= inv;
    }

#pragma unroll
    for (int i = 0; i < 6; i++) {
        float2 acc = make_float2(0.f, 0.f);
#pragma unroll
        for (int j = 0; j < 6; j++) {
            acc.x += s[i][j] * v[j].x;
            acc.y += s[i][j] * v[j].y;
        }
        *(float2*)(C + base + (size_t)i * NTOK * E_DIM) = acc;
    }
}

// ---------------------------------------------------------------------------
// Block-wide allreduce of (sum, sumsq)
// ---------------------------------------------------------------------------
__device__ __forceinline__ float2 blockAllReduce2(float2 v)
{
    __shared__ float2 sh[8];
    const int lane = threadIdx.x & 31;
    const int wid  = threadIdx.x >> 5;
#pragma unroll
    for (int o = 16; o; o >>= 1) {
        v.x += __shfl_xor_sync(0xffffffffu, v.x, o);
        v.y += __shfl_xor_sync(0xffffffffu, v.y, o);
    }
    if (lane == 0) sh[wid] = v;
    __syncthreads();
    if (wid == 0) {
        float2 t = (lane < 8) ? sh[lane] : make_float2(0.f, 0.f);
#pragma unroll
        for (int o = 4; o; o >>= 1) {
            t.x += __shfl_xor_sync(0xffffffffu, t.x, o);
            t.y += __shfl_xor_sync(0xffffffffu, t.y, o);
        }
        if (lane == 0) sh[0] = t;
    }
    __syncthreads();
    float2 r = sh[0];
    __syncthreads();
    return r;
}

// ---------------------------------------------------------------------------
// LN1(out + st) per (j, n) row, then weighted fusion over j -> F[n, 1024]
// One block per token n; 256 threads x float4.
// ---------------------------------------------------------------------------
__global__ __launch_bounds__(256)
void ln1_fuse_kernel(const float* __restrict__ OP, const float* __restrict__ ST,
                     const float* __restrict__ g, const float* __restrict__ b,
                     const float* __restrict__ fw, float* __restrict__ F)
{
    const int n   = blockIdx.x;
    const int tid = threadIdx.x;

    // softmax of fusion weights (6 values, each thread redundantly)
    float w[6];
    {
        float f[6], mx = -1e30f;
#pragma unroll
        for (int j = 0; j < 6; j++) { f[j] = fw[j]; mx = fmaxf(mx, f[j]); }
        float se = 0.f;
#pragma unroll
        for (int j = 0; j < 6; j++) { w[j] = expf(f[j] - mx); se += w[j]; }
        float inv = 1.f / se;
#pragma unroll
        for (int j = 0; j < 6; j++) w[j] *= inv;
    }

    float4 gg = ((const float4*)g)[tid];
    float4 bb = ((const float4*)b)[tid];
    float4 acc = make_float4(0.f, 0.f, 0.f, 0.f);

    for (int j = 0; j < 6; j++) {
        size_t roff = ((size_t)j * NTOK + n) * E_DIM;
        float4 x = ((const float4*)(OP + roff))[tid];
        float4 y = ((const float4*)(ST + roff))[tid];
        x.x += y.x; x.y += y.y; x.z += y.z; x.w += y.w;

        float2 r = make_float2(x.x + x.y + x.z + x.w,
                               x.x * x.x + x.y * x.y + x.z * x.z + x.w * x.w);
        r = blockAllReduce2(r);
        float mean = r.x * (1.f / 1024.f);
        float var  = r.y * (1.f / 1024.f) - mean * mean;
        float rstd = rsqrtf(var + 1e-5f);

        acc.x += w[j] * ((x.x - mean) * rstd * gg.x + bb.x);
        acc.y += w[j] * ((x.y - mean) * rstd * gg.y + bb.y);
        acc.z += w[j] * ((x.z - mean) * rstd * gg.z + bb.z);
        acc.w += w[j] * ((x.w - mean) * rstd * gg.w + bb.w);
    }
    ((float4*)F)[(size_t)n * 256 + tid] = acc;
}

// ---------------------------------------------------------------------------
// LN2 per token row (hidden already has bias + LeakyReLU applied)
// ---------------------------------------------------------------------------
__global__ __launch_bounds__(256)
void ln2_kernel(const float* __restrict__ Hbuf, const float* __restrict__ g,
                const float* __restrict__ b, float* __restrict__ out)
{
    const int n   = blockIdx.x;
    const int tid = threadIdx.x;

    float4 x = ((const float4*)(Hbuf + (size_t)n * HID))[tid];
    float2 r = make_float2(x.x + x.y + x.z + x.w,
                           x.x * x.x + x.y * x.y + x.z * x.z + x.w * x.w);
    r = blockAllReduce2(r);
    float mean = r.x * (1.f / 1024.f);
    float var  = r.y * (1.f / 1024.f) - mean * mean;
    float rstd = rsqrtf(var + 1e-5f);

    float4 gg = ((const float4*)g)[tid];
    float4 bb = ((const float4*)b)[tid];
    float4 o;
    o.x = (x.x - mean) * rstd * gg.x + bb.x;
    o.y = (x.y - mean) * rstd * gg.y + bb.y;
    o.z = (x.z - mean) * rstd * gg.z + bb.z;
    o.w = (x.w - mean) * rstd * gg.w + bb.w;
    ((float4*)(out + (size_t)n * HID))[tid] = o;
}

// ---------------------------------------------------------------------------
// Launch
// ---------------------------------------------------------------------------
extern "C" void kernel_launch(void* const* d_in, const int* in_sizes, int n_in,
                              void* d_out, int out_size)
{
    const float* st    = (const float*)d_in[0];
    const float* Wq    = (const float*)d_in[1];
    const float* bq    = (const float*)d_in[2];
    const float* Wk    = (const float*)d_in[3];
    const float* bk    = (const float*)d_in[4];
    const float* Wv    = (const float*)d_in[5];
    const float* bv    = (const float*)d_in[6];
    const float* Wo    = (const float*)d_in[7];
    const float* bo    = (const float*)d_in[8];
    const float* ln1_g = (const float*)d_in[9];
    const float* ln1_b = (const float*)d_in[10];
    const float* fw    = (const float*)d_in[11];
    const float* Wf    = (const float*)d_in[12];
    const float* bf    = (const float*)d_in[13];
    const float* ln2_g = (const float*)d_in[14];
    const float* ln2_b = (const float*)d_in[15];
    float* out = (float*)d_out;

    void* sp = nullptr;
    cudaGetSymbolAddress(&sp, g_scratch);
    float* S = (float*)sp;

    dim3 blk(256);
    dim3 gBig(E_DIM / BN, NROWS / BM);     // (8, 384)
    dim3 gF(HID / BN, NTOK / BM);          // (8, 64)

    // QKV projections: (49152x1024) @ (1024x1024)^T
    sgemm_nt<<<gBig, blk>>>(st, Wq, bq, S + OFF_Q, NROWS, E_DIM, E_DIM, 0);
    sgemm_nt<<<gBig, blk>>>(st, Wk, bk, S + OFF_K, NROWS, E_DIM, E_DIM, 0);
    sgemm_nt<<<gBig, blk>>>(st, Wv, bv, S + OFF_V, NROWS, E_DIM, E_DIM, 0);

    // 6x6 attention per (token, head): 8192*16 warps, 8 warps/block
    attn6_kernel<<<(NTOK * H_HEADS) / 8, blk>>>(S + OFF_Q, S + OFF_K, S + OFF_V,
                                                S + OFF_C);

    // Output projection (writes over Q buffer)
    sgemm_nt<<<gBig, blk>>>(S + OFF_C, Wo, bo, S + OFF_O, NROWS, E_DIM, E_DIM, 0);

    // LN1(out + st) + weighted fusion over the 6 states -> F (8192x1024)
    ln1_fuse_kernel<<<NTOK, blk>>>(S + OFF_O, st, ln1_g, ln1_b, fw, S + OFF_F);

    // Final projection + bias + LeakyReLU -> H
    sgemm_nt<<<gF, blk>>>(S + OFF_F, Wf, bf, S + OFF_H, NTOK, HID, E_DIM, 1);

    // LN2 -> output
    ln2_kernel<<<NTOK, blk>>>(S + OFF_H, ln2_g, ln2_b, out);
}